// round 8
// baseline (speedup 1.0000x reference)
#include <cuda_runtime.h>
#include <cuda_bf16.h>
#include <math.h>
#include <stdint.h>

// Problem constants (match reference)
#define NN      50000
#define EE      600000
#define D_IN    128
#define D_H     128
#define D_OUT   64
#define NLAYERS 3
#define NG      64
#define SLOPE   0.2f
#define CAP     64          // per-dst bucket capacity (Poisson(12): P(deg>=64)~1e-30)

// ---------------------------------------------------------------------------
// Device scratch
// ---------------------------------------------------------------------------
__device__ __align__(16) float g_h [NN * D_H];
__device__ __align__(16) float g_hp[NN * D_H];
__device__ float g_es[NN];
__device__ float g_ed[NN];
__device__ float g_ee[NN * CAP];                // cached per-edge leaky scores (bucketed)
__device__ int   g_cur[NN];                     // bucket fill count == degree
__device__ int   g_csrc[NN * CAP];              // bucketed-by-dst source ids
__device__ int   g_is64;

__device__ __forceinline__ float leaky(float x) {
    return x >= 0.f ? x : SLOPE * x;
}

__device__ __forceinline__ int load_idx(const void* p, long long i) {
    return g_is64 ? (int)((const long long*)p)[i] : ((const int*)p)[i];
}

// pack two floats as bf16x2: low half = a (even k), high half = b (odd k)
__device__ __forceinline__ uint32_t pack_bf16(float a, float b) {
    uint32_t r;
    asm("cvt.rn.bf16x2.f32 %0, %1, %2;" : "=r"(r) : "f"(b), "f"(a));
    return r;
}

__device__ __forceinline__ float bf16_hi_val(float x) {
    __nv_bfloat16 h = __float2bfloat16_rn(x);
    return __bfloat162float(h);
}

__device__ __forceinline__ void mma_bf16(float c[4], const uint32_t a[4],
                                         uint32_t b0, uint32_t b1) {
    asm volatile(
        "mma.sync.aligned.m16n8k16.row.col.f32.bf16.bf16.f32 "
        "{%0,%1,%2,%3}, {%4,%5,%6,%7}, {%8,%9}, {%0,%1,%2,%3};\n"
        : "+f"(c[0]), "+f"(c[1]), "+f"(c[2]), "+f"(c[3])
        : "r"(a[0]), "r"(a[1]), "r"(a[2]), "r"(a[3]), "r"(b0), "r"(b1));
}

// ---------------------------------------------------------------------------
// init: zero bucket cursors; parallel index-dtype probe (one warp, ballot)
// int64 node ids < 50000 -> every odd 32-bit word is 0; int32 -> random ids.
// ---------------------------------------------------------------------------
__global__ void k_init(const int* __restrict__ eiw) {
    int i = blockIdx.x * blockDim.x + threadIdx.x;
    if (i < NN) g_cur[i] = 0;
    if (blockIdx.x == 0 && threadIdx.x < 32) {
        int lane = threadIdx.x;
        int nz = (eiw[2 * lane + 1] != 0) | (eiw[2 * (lane + 32) + 1] != 0);
        unsigned bal = __ballot_sync(0xffffffffu, nz);
        if (lane == 0) g_is64 = (bal == 0u);
    }
}

// ---------------------------------------------------------------------------
// Single-pass bucketed CSR: scatter edges directly into per-dst slots
// ---------------------------------------------------------------------------
__global__ void k_scatter(const void* __restrict__ ei) {
    int e = blockIdx.x * blockDim.x + threadIdx.x;
    if (e < EE) {
        int s = load_idx(ei, e);
        int d = load_idx(ei, (long long)EE + e);
        if ((unsigned)d < NN && (unsigned)s < NN) {
            int pos = atomicAdd(&g_cur[d], 1);
            if (pos < CAP) g_csrc[d * CAP + pos] = s;
        }
    }
}

// ---------------------------------------------------------------------------
// 3xBF16 tensor-core GEMM: C[M,128] = A[M,128] @ B[128,128] (+bias)
// Block 128x128, 256 threads (8 warps, 2x4), warp tile 64x32, BK=16.
// Optional fused epilogue: es/ed row-dots with asrc/adst.
// ---------------------------------------------------------------------------
#define PAD 136

template <bool FUSE_ESED>
__device__ __forceinline__ void mma_gemm_body(const float* __restrict__ A,
                                              const float* __restrict__ B,
                                              const float* __restrict__ bias,
                                              const float* __restrict__ asrc,
                                              const float* __restrict__ adst,
                                              float* __restrict__ C, int M) {
    __shared__ uint32_t Ah[8][PAD], Al[8][PAD];   // [k-pair][m]
    __shared__ uint32_t Bh[8][PAD], Bl[8][PAD];   // [k-pair][n]
    __shared__ float es_s[128], ed_s[128];

    const int tid  = threadIdx.x;
    const int warp = tid >> 5, lane = tid & 31;
    const int wm = warp >> 2, wn = warp & 3;
    const int gid = lane >> 2, tig = lane & 3;
    const int brow = blockIdx.x * 128;

    if (FUSE_ESED && tid < 128) { es_s[tid] = 0.f; ed_s[tid] = 0.f; }

    const int a_r  = tid & 63;
    const int a_kq = (tid >> 6) * 4;
    const int b_bp = tid >> 5;
    const int b_n  = (tid & 31) * 4;

    float acc[4][4][4];
    #pragma unroll
    for (int mt = 0; mt < 4; mt++)
        #pragma unroll
        for (int nt = 0; nt < 4; nt++)
            #pragma unroll
            for (int c = 0; c < 4; c++) acc[mt][nt][c] = 0.f;

    for (int kc = 0; kc < 128; kc += 16) {
        #pragma unroll
        for (int p = 0; p < 2; p++) {
            int r = a_r + 64 * p;
            int grow = brow + r;
            float4 v = (grow < M) ? *(const float4*)&A[(size_t)grow * 128 + kc + a_kq]
                                  : make_float4(0.f, 0.f, 0.f, 0.f);
            float f[4] = {v.x, v.y, v.z, v.w};
            float h[4], l[4];
            #pragma unroll
            for (int i = 0; i < 4; i++) {
                h[i] = bf16_hi_val(f[i]);
                l[i] = f[i] - h[i];
            }
            Ah[a_kq / 2][r]     = pack_bf16(h[0], h[1]);
            Ah[a_kq / 2 + 1][r] = pack_bf16(h[2], h[3]);
            Al[a_kq / 2][r]     = pack_bf16(l[0], l[1]);
            Al[a_kq / 2 + 1][r] = pack_bf16(l[2], l[3]);
        }
        {
            const float* B0 = &B[(size_t)(kc + 2 * b_bp) * 128 + b_n];
            float4 r0 = *(const float4*)B0;
            float4 r1 = *(const float4*)(B0 + 128);
            float f0[4] = {r0.x, r0.y, r0.z, r0.w};
            float f1[4] = {r1.x, r1.y, r1.z, r1.w};
            uint4 hq, lq;
            uint32_t* hp_ = (uint32_t*)&hq;
            uint32_t* lp_ = (uint32_t*)&lq;
            #pragma unroll
            for (int i = 0; i < 4; i++) {
                float h0 = bf16_hi_val(f0[i]), l0 = f0[i] - h0;
                float h1 = bf16_hi_val(f1[i]), l1 = f1[i] - h1;
                hp_[i] = pack_bf16(h0, h1);
                lp_[i] = pack_bf16(l0, l1);
            }
            *(uint4*)&Bh[b_bp][b_n] = hq;
            *(uint4*)&Bl[b_bp][b_n] = lq;
        }
        __syncthreads();

        {
            uint32_t ah[4][4], al[4][4];
            #pragma unroll
            for (int mt = 0; mt < 4; mt++) {
                int m0 = wm * 64 + mt * 16 + gid;
                ah[mt][0] = Ah[tig][m0];     ah[mt][1] = Ah[tig][m0 + 8];
                ah[mt][2] = Ah[tig + 4][m0]; ah[mt][3] = Ah[tig + 4][m0 + 8];
                al[mt][0] = Al[tig][m0];     al[mt][1] = Al[tig][m0 + 8];
                al[mt][2] = Al[tig + 4][m0]; al[mt][3] = Al[tig + 4][m0 + 8];
            }
            #pragma unroll
            for (int nt = 0; nt < 4; nt++) {
                int n0 = wn * 32 + nt * 8 + gid;
                uint32_t bh0 = Bh[tig][n0], bh1 = Bh[tig + 4][n0];
                uint32_t bl0 = Bl[tig][n0], bl1 = Bl[tig + 4][n0];
                #pragma unroll
                for (int mt = 0; mt < 4; mt++) {
                    mma_bf16(acc[mt][nt], ah[mt], bh0, bh1);
                    mma_bf16(acc[mt][nt], ah[mt], bl0, bl1);
                    mma_bf16(acc[mt][nt], al[mt], bh0, bh1);
                }
            }
        }
        __syncthreads();
    }

    float as_v[4][2], ad_v[4][2];
    if (FUSE_ESED) {
        #pragma unroll
        for (int nt = 0; nt < 4; nt++) {
            int c0 = wn * 32 + nt * 8 + 2 * tig;
            as_v[nt][0] = asrc[c0]; as_v[nt][1] = asrc[c0 + 1];
            ad_v[nt][0] = adst[c0]; ad_v[nt][1] = adst[c0 + 1];
        }
    }

    #pragma unroll
    for (int mt = 0; mt < 4; mt++) {
        int r0 = brow + wm * 64 + mt * 16 + gid;
        float pe0 = 0.f, pe1 = 0.f, pd0 = 0.f, pd1 = 0.f;
        #pragma unroll
        for (int nt = 0; nt < 4; nt++) {
            int c0 = wn * 32 + nt * 8 + 2 * tig;
            float b0v = bias ? bias[c0]     : 0.f;
            float b1v = bias ? bias[c0 + 1] : 0.f;
            float v00 = acc[mt][nt][0] + b0v, v01 = acc[mt][nt][1] + b1v;
            float v10 = acc[mt][nt][2] + b0v, v11 = acc[mt][nt][3] + b1v;
            if (r0 < M)     *(float2*)&C[(size_t)r0 * 128 + c0]       = make_float2(v00, v01);
            if (r0 + 8 < M) *(float2*)&C[(size_t)(r0 + 8) * 128 + c0] = make_float2(v10, v11);
            if (FUSE_ESED) {
                pe0 += v00 * as_v[nt][0] + v01 * as_v[nt][1];
                pe1 += v10 * as_v[nt][0] + v11 * as_v[nt][1];
                pd0 += v00 * ad_v[nt][0] + v01 * ad_v[nt][1];
                pd1 += v10 * ad_v[nt][0] + v11 * ad_v[nt][1];
            }
        }
        if (FUSE_ESED) {
            #pragma unroll
            for (int o = 1; o <= 2; o <<= 1) {
                pe0 += __shfl_xor_sync(0xffffffffu, pe0, o);
                pe1 += __shfl_xor_sync(0xffffffffu, pe1, o);
                pd0 += __shfl_xor_sync(0xffffffffu, pd0, o);
                pd1 += __shfl_xor_sync(0xffffffffu, pd1, o);
            }
            if (tig == 0) {
                int lr = wm * 64 + mt * 16 + gid;
                atomicAdd(&es_s[lr], pe0);     atomicAdd(&es_s[lr + 8], pe1);
                atomicAdd(&ed_s[lr], pd0);     atomicAdd(&ed_s[lr + 8], pd1);
            }
        }
    }

    if (FUSE_ESED) {
        __syncthreads();
        if (tid < 128 && brow + tid < M) {
            g_es[brow + tid] = es_s[tid];
            g_ed[brow + tid] = ed_s[tid];
        }
    }
}

__global__ void __launch_bounds__(256) k_mma_x(const float* __restrict__ A,
                                               const float* __restrict__ B,
                                               const float* __restrict__ bias) {
    mma_gemm_body<false>(A, B, bias, nullptr, nullptr, g_h, NN);
}

__global__ void __launch_bounds__(256) k_mma_h(const float* __restrict__ B,
                                               const float* __restrict__ asrc,
                                               const float* __restrict__ adst) {
    mma_gemm_body<true>(g_h, B, nullptr, asrc, adst, g_hp, NN);
}

// ---------------------------------------------------------------------------
// GAT aggregation (warp per destination node, bucketed edge lists)
// ---------------------------------------------------------------------------
__global__ void k_gat_aggr(const float* __restrict__ bg) {
    int warp = (blockIdx.x * blockDim.x + threadIdx.x) >> 5;
    int lane = threadIdx.x & 31;
    if (warp >= NN) return;
    const int d = warp;
    const int lo = d * CAP;
    const int deg = g_cur[d];
    const int hi = lo + (deg < CAP ? deg : CAP);
    const float es_d = g_es[d], ed_d = g_ed[d];
    const float e_self = leaky(es_d + ed_d);

    // pass 1: edge scores + segment max
    float m = e_self;
    for (int j = lo + lane; j < hi; j += 32) {
        int s = g_csrc[j];
        float e = leaky(g_es[s] + ed_d);
        g_ee[j] = e;
        m = fmaxf(m, e);
    }
    #pragma unroll
    for (int o = 16; o; o >>= 1) m = fmaxf(m, __shfl_xor_sync(0xffffffffu, m, o));

    const float4* hp4 = (const float4*)g_hp;
    float4* h4 = (float4*)g_h;

    // pass 2: unnormalized weighted sum + z
    float ex_self = expf(e_self - m);
    float z = ex_self;
    float4 v = hp4[(size_t)d * 32 + lane];
    float4 acc;
    acc.x = ex_self * v.x; acc.y = ex_self * v.y;
    acc.z = ex_self * v.z; acc.w = ex_self * v.w;

    for (int j = lo; j < hi; ++j) {
        int s = g_csrc[j];
        float ex = expf(g_ee[j] - m);
        z += ex;
        float4 w = hp4[(size_t)s * 32 + lane];
        acc.x = fmaf(ex, w.x, acc.x);
        acc.y = fmaf(ex, w.y, acc.y);
        acc.z = fmaf(ex, w.z, acc.z);
        acc.w = fmaf(ex, w.w, acc.w);
    }
    const float invz = 1.0f / z;

    float4 b = ((const float4*)bg)[lane];
    float4 hin = h4[(size_t)d * 32 + lane];
    float4 o;
    o.x = fmaxf(fmaf(acc.x, invz, b.x), 0.f) + hin.x;
    o.y = fmaxf(fmaf(acc.y, invz, b.y), 0.f) + hin.y;
    o.z = fmaxf(fmaf(acc.z, invz, b.z), 0.f) + hin.z;
    o.w = fmaxf(fmaf(acc.w, invz, b.w), 0.f) + hin.w;
    h4[(size_t)d * 32 + lane] = o;
}

// ---------------------------------------------------------------------------
// Fused pool + final projection: block per graph (batch sorted)
// ---------------------------------------------------------------------------
__global__ void k_poolfinal(const void* __restrict__ batch,
                            const float* __restrict__ W2,
                            const float* __restrict__ b2,
                            float* __restrict__ out) {
    __shared__ float ps[128];
    __shared__ int s_lo, s_hi;
    const int g = blockIdx.x;
    const int tid = threadIdx.x;
    if (tid == 0) {
        int lo = 0, hi = NN;
        while (lo < hi) { int mid = (lo + hi) >> 1; if (load_idx(batch, mid) < g) lo = mid + 1; else hi = mid; }
        s_lo = lo;
        lo = 0; hi = NN;
        int g1 = g + 1;
        while (lo < hi) { int mid = (lo + hi) >> 1; if (load_idx(batch, mid) < g1) lo = mid + 1; else hi = mid; }
        s_hi = lo;
    }
    __syncthreads();
    float acc = 0.f;
    for (int i = s_lo; i < s_hi; ++i) acc += g_h[(size_t)i * 128 + tid];
    ps[tid] = acc;
    __syncthreads();
    if (tid < 64) {
        float o = b2[tid];
        #pragma unroll 8
        for (int k = 0; k < 128; ++k)
            o = fmaf(ps[k], W2[k * 64 + tid], o);
        out[g * 64 + tid] = o;
    }
}

// ---------------------------------------------------------------------------
// Launch
// ---------------------------------------------------------------------------
extern "C" void kernel_launch(void* const* d_in, const int* in_sizes, int n_in,
                              void* d_out, int out_size) {
    const float* x     = (const float*)d_in[0];
    const void*  ei    = d_in[1];
    const void*  batch = d_in[2];
    const float* W1    = (const float*)d_in[3];
    const float* b1    = (const float*)d_in[4];
    const float* Wg    = (const float*)d_in[5];
    const float* asrc  = (const float*)d_in[6];
    const float* adst  = (const float*)d_in[7];
    const float* bg    = (const float*)d_in[8];
    const float* W2    = (const float*)d_in[9];
    const float* b2    = (const float*)d_in[10];
    float*       out   = (float*)d_out;

    k_init<<<(NN + 255) / 256, 256>>>((const int*)ei);
    k_scatter<<<(EE + 255) / 256, 256>>>(ei);

    const int gemm_blocks = (NN + 127) / 128;
    const int node_warp_blocks = (NN * 32 + 255) / 256;

    k_mma_x<<<gemm_blocks, 256>>>(x, W1, b1);

    for (int l = 0; l < NLAYERS; ++l) {
        k_mma_h<<<gemm_blocks, 256>>>(Wg + (size_t)l * 128 * 128,
                                      asrc + l * 128, adst + l * 128);
        k_gat_aggr<<<node_warp_blocks, 256>>>(bg + l * 128);
    }

    k_poolfinal<<<NG, 128>>>(batch, W2, b2, out);
}